// round 1
// baseline (speedup 1.0000x reference)
#include <cuda_runtime.h>
#include <cstdint>

#define D 300
#define TWO_D 600
#define NLAYERS 5
#define MAXN 200000
#define MAXE 400000
#define MAXG 1024
#define BN_EPS 1e-5f

// ---------------- scratch (allocation-free: __device__ globals) ----------------
__device__ float g_h[(size_t)MAXN * D];        // 240 MB
__device__ float g_agg[(size_t)MAXN * D];      // 240 MB
__device__ float g_t[(size_t)MAXN * TWO_D];    // 480 MB
__device__ float g_gavg[(size_t)MAXG * D];

// ---------------- zero ----------------
__global__ void zero_kernel(float4* __restrict__ p, int n4) {
    int i = blockIdx.x * blockDim.x + threadIdx.x;
    if (i < n4) p[i] = make_float4(0.f, 0.f, 0.f, 0.f);
}

// ---------------- h0 = node_emb0[an] + node_emb1[ct] ----------------
__global__ void init_h_kernel(const int* __restrict__ an, const int* __restrict__ ct,
                              const float* __restrict__ e0, const float* __restrict__ e1,
                              float* __restrict__ h, int N) {
    int idx = blockIdx.x * blockDim.x + threadIdx.x;
    if (idx >= N * D) return;
    int n = idx / D;
    int d = idx - n * D;
    h[idx] = e0[an[n] * D + d] + e1[ct[n] * D + d];
}

// ---------------- scatter: agg[dst] += h[src] + e0[bt] + e1[bdt] ----------------
// one thread per (edge, float4-chunk); D = 300 = 75 float4
__global__ void scatter_kernel(const float* __restrict__ h,
                               const int* __restrict__ src, const int* __restrict__ dst,
                               const int* __restrict__ bt, const int* __restrict__ bdt,
                               const float* __restrict__ e0, const float* __restrict__ e1,
                               float* __restrict__ agg, int E) {
    int idx = blockIdx.x * blockDim.x + threadIdx.x;
    if (idx >= E * 75) return;
    int e = idx / 75;
    int c = idx - e * 75;
    int s = src[e];
    float4 hv  = *(const float4*)(h + (size_t)s * D + c * 4);
    float4 ev0 = *(const float4*)(e0 + (size_t)bt[e] * D + c * 4);
    float4 ev1 = *(const float4*)(e1 + (size_t)bdt[e] * D + c * 4);
    float* out = agg + (size_t)dst[e] * D + c * 4;
    atomicAdd(out + 0, hv.x + ev0.x + ev1.x);
    atomicAdd(out + 1, hv.y + ev0.y + ev1.y);
    atomicAdd(out + 2, hv.z + ev0.z + ev1.z);
    atomicAdd(out + 3, hv.w + ev0.w + ev1.w);
}

// ---------------- GEMM: C = epilogue(A[M,K] @ B[K,Nc] + bias) ----------------
// MODE 0: bias; 1: bias+relu; 2: bias+bn; 3: bias+bn+relu
template <int MODE>
__global__ __launch_bounds__(256)
void gemm_kernel(const float* __restrict__ A, const float* __restrict__ B,
                 const float* __restrict__ bias,
                 const float* __restrict__ bng, const float* __restrict__ bnb,
                 const float* __restrict__ bnm, const float* __restrict__ bnv,
                 float* __restrict__ C, int M, int K, int Nc) {
    __shared__ float As[16][68];   // [k][row], padded for bank conflicts + alignment
    __shared__ float Bs[16][64];   // [k][col]

    const int tid = threadIdx.x;
    const int tx = tid & 15;       // 0..15 -> cols
    const int ty = tid >> 4;       // 0..15 -> rows
    const int rowBase = blockIdx.y * 64;
    const int colBase = blockIdx.x * 64;

    float acc[4][4];
#pragma unroll
    for (int i = 0; i < 4; i++)
#pragma unroll
        for (int j = 0; j < 4; j++) acc[i][j] = 0.f;

    const int aRow = tid >> 2;           // 0..63
    const int aK4  = (tid & 3) * 4;      // 0,4,8,12
    const int bRow = tid >> 4;           // 0..15
    const int bC4  = (tid & 15) * 4;     // 0..60

    for (int k0 = 0; k0 < K; k0 += 16) {
        // load A tile (64 x 16), stored transposed
        float4 av = make_float4(0.f, 0.f, 0.f, 0.f);
        {
            int ar = rowBase + aRow;
            int ak = k0 + aK4;
            if (ar < M && ak < K)  // K % 4 == 0 so chunk is fully in-range
                av = *(const float4*)(A + (size_t)ar * K + ak);
        }
        As[aK4 + 0][aRow] = av.x;
        As[aK4 + 1][aRow] = av.y;
        As[aK4 + 2][aRow] = av.z;
        As[aK4 + 3][aRow] = av.w;
        // load B tile (16 x 64)
        float4 bv = make_float4(0.f, 0.f, 0.f, 0.f);
        {
            int br = k0 + bRow;
            int bc = colBase + bC4;
            if (br < K && bc < Nc)
                bv = *(const float4*)(B + (size_t)br * Nc + bc);
        }
        *(float4*)&Bs[bRow][bC4] = bv;
        __syncthreads();

#pragma unroll
        for (int kk = 0; kk < 16; kk++) {
            float a[4], b[4];
#pragma unroll
            for (int i = 0; i < 4; i++) a[i] = As[kk][ty * 4 + i];
#pragma unroll
            for (int j = 0; j < 4; j++) b[j] = Bs[kk][tx * 4 + j];
#pragma unroll
            for (int i = 0; i < 4; i++)
#pragma unroll
                for (int j = 0; j < 4; j++) acc[i][j] += a[i] * b[j];
        }
        __syncthreads();
    }

    // epilogue
#pragma unroll
    for (int j = 0; j < 4; j++) {
        int c = colBase + tx * 4 + j;
        if (c >= Nc) continue;
        float bia = bias[c];
        float scale = 1.f, shift = 0.f;
        if (MODE >= 2) {
            scale = bng[c] * rsqrtf(bnv[c] + BN_EPS);
            shift = bnb[c] - bnm[c] * scale;
        }
#pragma unroll
        for (int i = 0; i < 4; i++) {
            int r = rowBase + ty * 4 + i;
            if (r >= M) continue;
            float v = acc[i][j] + bia;
            if (MODE >= 2) v = v * scale + shift;
            if (MODE == 1 || MODE == 3) v = fmaxf(v, 0.f);
            C[(size_t)r * Nc + c] = v;
        }
    }
}

// ---------------- avg pool per graph (graph_ids is sorted -> contiguous ranges) ----------------
__device__ __forceinline__ int lower_bound_dev(const int* a, int n, int v) {
    int lo = 0, hi = n;
    while (lo < hi) {
        int m = (lo + hi) >> 1;
        if (a[m] < v) lo = m + 1; else hi = m;
    }
    return lo;
}

__global__ void pool_kernel(const float* __restrict__ h, const int* __restrict__ gid,
                            float* __restrict__ gavg, int N) {
    __shared__ int sh[2];
    int g = blockIdx.x;
    if (threadIdx.x == 0) sh[0] = lower_bound_dev(gid, N, g);
    if (threadIdx.x == 1) sh[1] = lower_bound_dev(gid, N, g + 1);
    __syncthreads();
    int lo = sh[0], hi = sh[1];
    int d = threadIdx.x;
    if (d >= D) return;
    float s = 0.f;
    for (int n = lo; n < hi; n++) s += h[(size_t)n * D + d];
    float cnt = (float)(hi - lo);
    gavg[(size_t)g * D + d] = s / fmaxf(cnt, 1.0f);
}

// ---------------- launch ----------------
extern "C" void kernel_launch(void* const* d_in, const int* in_sizes, int n_in,
                              void* d_out, int out_size) {
    const int* an  = (const int*)d_in[0];
    const int* ct  = (const int*)d_in[1];
    const int* bt  = (const int*)d_in[2];
    const int* bdt = (const int*)d_in[3];
    const int* src = (const int*)d_in[4];
    const int* dst = (const int*)d_in[5];
    const int* gid = (const int*)d_in[6];
    const int N = in_sizes[0];
    const int E = in_sizes[2];

    // num_graphs may appear as a size-1 scalar tensor at index 7
    int p = 7;
    if (n_in > 7 && in_sizes[7] == 1) p = 8;
    const float* node_emb0 = (const float*)d_in[p + 0];
    const float* node_emb1 = (const float*)d_in[p + 1];
    const float* edge_emb0 = (const float*)d_in[p + 2];
    const float* edge_emb1 = (const float*)d_in[p + 3];
    const float* W1  = (const float*)d_in[p + 4];
    const float* b1  = (const float*)d_in[p + 5];
    const float* W2  = (const float*)d_in[p + 6];
    const float* b2  = (const float*)d_in[p + 7];
    const float* bng = (const float*)d_in[p + 8];
    const float* bnb = (const float*)d_in[p + 9];
    const float* bnm = (const float*)d_in[p + 10];
    const float* bnv = (const float*)d_in[p + 11];
    const float* Wd  = (const float*)d_in[p + 12];
    const float* bd  = (const float*)d_in[p + 13];
    const int G = out_size / 256;

    float *h, *agg, *t, *gavg;
    cudaGetSymbolAddress((void**)&h, g_h);
    cudaGetSymbolAddress((void**)&agg, g_agg);
    cudaGetSymbolAddress((void**)&t, g_t);
    cudaGetSymbolAddress((void**)&gavg, g_gavg);

    const int ND = N * D;

    init_h_kernel<<<(ND + 255) / 256, 256>>>(an, ct, node_emb0, node_emb1, h, N);

    for (int l = 0; l < NLAYERS; l++) {
        zero_kernel<<<(ND / 4 + 255) / 256, 256>>>((float4*)agg, ND / 4);
        scatter_kernel<<<(E * 75 + 255) / 256, 256>>>(
            h, src, dst, bt, bdt,
            edge_emb0 + (size_t)l * 6 * D, edge_emb1 + (size_t)l * 3 * D, agg, E);
        // t = relu(agg @ W1[l] + b1[l])      [N, 600]
        gemm_kernel<1><<<dim3((TWO_D + 63) / 64, (N + 63) / 64), 256>>>(
            agg, W1 + (size_t)l * D * TWO_D, b1 + (size_t)l * TWO_D,
            nullptr, nullptr, nullptr, nullptr, t, N, D, TWO_D);
        // h = [relu(]bn(t @ W2[l] + b2[l])[)]   [N, 300]
        if (l < NLAYERS - 1) {
            gemm_kernel<3><<<dim3((D + 63) / 64, (N + 63) / 64), 256>>>(
                t, W2 + (size_t)l * TWO_D * D, b2 + (size_t)l * D,
                bng + (size_t)l * D, bnb + (size_t)l * D,
                bnm + (size_t)l * D, bnv + (size_t)l * D, h, N, TWO_D, D);
        } else {
            gemm_kernel<2><<<dim3((D + 63) / 64, (N + 63) / 64), 256>>>(
                t, W2 + (size_t)l * TWO_D * D, b2 + (size_t)l * D,
                bng + (size_t)l * D, bnb + (size_t)l * D,
                bnm + (size_t)l * D, bnv + (size_t)l * D, h, N, TWO_D, D);
        }
    }

    pool_kernel<<<G, 320>>>(h, gid, gavg, N);
    // out = gavg @ Wd + bd   [G, 256]
    gemm_kernel<0><<<dim3((256 + 63) / 64, (G + 63) / 64), 256>>>(
        gavg, Wd, bd, nullptr, nullptr, nullptr, nullptr,
        (float*)d_out, G, D, 256);
}

// round 2
// speedup vs baseline: 1.0668x; 1.0668x over previous
#include <cuda_runtime.h>
#include <cstdint>

#define D 300
#define TWO_D 600
#define NLAYERS 5
#define MAXN 200000
#define MAXG 1024
#define BN_EPS 1e-5f

// ---------------- scratch (allocation-free: __device__ globals) ----------------
__device__ float g_h[(size_t)MAXN * D];        // 240 MB
__device__ float g_agg[(size_t)MAXN * D];      // 240 MB
__device__ float g_t[(size_t)MAXN * TWO_D];    // 480 MB
__device__ float g_cnt0[(size_t)MAXN * 6];
__device__ float g_cnt1[(size_t)MAXN * 3];
__device__ float g_gavg[(size_t)MAXG * D];

// ---------------- helpers ----------------
__device__ __forceinline__ float tf32_rna(float x) {
    uint32_t u;
    asm("cvt.rna.tf32.f32 %0, %1;" : "=r"(u) : "f"(x));
    return __uint_as_float(u);
}

// ---------------- zero ----------------
__global__ void zero_kernel(float* __restrict__ p, int n) {
    int i = blockIdx.x * blockDim.x + threadIdx.x;
    if (i < n) p[i] = 0.f;
}

// ---------------- h0 = node_emb0[an] + node_emb1[ct] ----------------
__global__ void init_h_kernel(const int* __restrict__ an, const int* __restrict__ ct,
                              const float* __restrict__ e0, const float* __restrict__ e1,
                              float* __restrict__ h, int N) {
    int idx = blockIdx.x * blockDim.x + threadIdx.x;
    if (idx >= N * D) return;
    int n = idx / D;
    int d = idx - n * D;
    h[idx] = e0[an[n] * D + d] + e1[ct[n] * D + d];
}

// ---------------- per-dst counts of bond-type / bond-direction ----------------
__global__ void count_kernel(const int* __restrict__ bt, const int* __restrict__ bdt,
                             const int* __restrict__ dst,
                             float* __restrict__ cnt0, float* __restrict__ cnt1, int E) {
    int e = blockIdx.x * blockDim.x + threadIdx.x;
    if (e >= E) return;
    int d = dst[e];
    atomicAdd(&cnt0[d * 6 + bt[e]], 1.f);
    atomicAdd(&cnt1[d * 3 + bdt[e]], 1.f);
}

// ---------------- agg = cnt0 @ e0[l] + cnt1 @ e1[l] (replaces zero + edge-emb scatter) ----------------
__global__ void agg_init_kernel(const float* __restrict__ cnt0, const float* __restrict__ cnt1,
                                const float* __restrict__ e0, const float* __restrict__ e1,
                                float* __restrict__ agg, int N) {
    int idx = blockIdx.x * blockDim.x + threadIdx.x;
    if (idx >= N * 75) return;
    int n = idx / 75;
    int c = idx - n * 75;
    float4 s = make_float4(0.f, 0.f, 0.f, 0.f);
#pragma unroll
    for (int b = 0; b < 6; b++) {
        float w = cnt0[n * 6 + b];
        if (w != 0.f) {
            float4 v = *(const float4*)(e0 + (size_t)b * D + c * 4);
            s.x += w * v.x; s.y += w * v.y; s.z += w * v.z; s.w += w * v.w;
        }
    }
#pragma unroll
    for (int b = 0; b < 3; b++) {
        float w = cnt1[n * 3 + b];
        if (w != 0.f) {
            float4 v = *(const float4*)(e1 + (size_t)b * D + c * 4);
            s.x += w * v.x; s.y += w * v.y; s.z += w * v.z; s.w += w * v.w;
        }
    }
    *(float4*)(agg + (size_t)n * D + c * 4) = s;
}

// ---------------- scatter: agg[dst] += h[src] via vectorized red ----------------
__global__ void scatter_h_kernel(const float* __restrict__ h,
                                 const int* __restrict__ src, const int* __restrict__ dst,
                                 float* __restrict__ agg, int E) {
    int idx = blockIdx.x * blockDim.x + threadIdx.x;
    if (idx >= E * 75) return;
    int e = idx / 75;
    int c = idx - e * 75;
    float4 hv = *(const float4*)(h + (size_t)src[e] * D + c * 4);
    float* out = agg + (size_t)dst[e] * D + c * 4;
    asm volatile("red.global.add.v4.f32 [%0], {%1,%2,%3,%4};"
                 :: "l"(out), "f"(hv.x), "f"(hv.y), "f"(hv.z), "f"(hv.w) : "memory");
}

// ---------------- TF32 tensor-core GEMM (3xTF32 split for fp32 accuracy) ----------------
// C = epilogue(A[M,K] @ B[K,Nc] + bias)
// MODE 0: bias; 1: bias+relu; 2: bias+bn; 3: bias+bn+relu
// Block tile 128x64, BK=16, 256 threads = 8 warps in 4(M) x 2(N), warp tile 32x32.
#define BM 128
#define BN 64
#define BK 16

template <int MODE>
__global__ __launch_bounds__(256)
void gemm_tf32_kernel(const float* __restrict__ A, const float* __restrict__ B,
                      const float* __restrict__ bias,
                      const float* __restrict__ bng, const float* __restrict__ bnb,
                      const float* __restrict__ bnm, const float* __restrict__ bnv,
                      float* __restrict__ C, int M, int K, int Nc) {
    __shared__ float Ah[BK][BM + 4];
    __shared__ float Al[BK][BM + 4];
    __shared__ float Bh[BK][BN + 4];
    __shared__ float Bl[BK][BN + 4];

    const int tid = threadIdx.x;
    const int lane = tid & 31;
    const int warp = tid >> 5;
    const int wm = warp >> 1;      // 0..3
    const int wn = warp & 1;       // 0..1
    const int g = lane >> 2;       // 0..7
    const int q = lane & 3;        // 0..3
    const int rowBase = blockIdx.y * BM;
    const int colBase = blockIdx.x * BN;

    float acc[2][4][4];
#pragma unroll
    for (int mt = 0; mt < 2; mt++)
#pragma unroll
        for (int nt = 0; nt < 4; nt++)
#pragma unroll
            for (int i = 0; i < 4; i++) acc[mt][nt][i] = 0.f;

    for (int k0 = 0; k0 < K; k0 += BK) {
        // ---- load A tile (128 x 16), split hi/lo, store transposed [k][m] ----
#pragma unroll
        for (int i = 0; i < 2; i++) {
            int id = tid + i * 256;
            int row = id >> 2;
            int kc = (id & 3) * 4;
            float4 v = make_float4(0.f, 0.f, 0.f, 0.f);
            int gr = rowBase + row;
            if (gr < M) {
                if (k0 + kc + 4 <= K) {
                    v = *(const float4*)(A + (size_t)gr * K + k0 + kc);
                } else {
                    const float* ap = A + (size_t)gr * K;
                    float tmp[4] = {0.f, 0.f, 0.f, 0.f};
#pragma unroll
                    for (int j = 0; j < 4; j++)
                        if (k0 + kc + j < K) tmp[j] = ap[k0 + kc + j];
                    v = make_float4(tmp[0], tmp[1], tmp[2], tmp[3]);
                }
            }
            float vv[4] = {v.x, v.y, v.z, v.w};
#pragma unroll
            for (int j = 0; j < 4; j++) {
                float hi = tf32_rna(vv[j]);
                Ah[kc + j][row] = hi;
                Al[kc + j][row] = vv[j] - hi;
            }
        }
        // ---- load B tile (16 x 64), split hi/lo ----
        {
            int r = tid >> 4;
            int c4 = (tid & 15) * 4;
            float4 v = make_float4(0.f, 0.f, 0.f, 0.f);
            int gk = k0 + r;
            int gc = colBase + c4;
            if (gk < K && gc < Nc)   // Nc % 4 == 0, so float4 chunk is all-in or all-out
                v = *(const float4*)(B + (size_t)gk * Nc + gc);
            float vv[4] = {v.x, v.y, v.z, v.w};
#pragma unroll
            for (int j = 0; j < 4; j++) {
                float hi = tf32_rna(vv[j]);
                Bh[r][c4 + j] = hi;
                Bl[r][c4 + j] = vv[j] - hi;
            }
        }
        __syncthreads();

        // ---- compute: 2 k-steps of 8, warp tile 32x32 = 2x4 mma tiles ----
#pragma unroll
        for (int ks = 0; ks < BK; ks += 8) {
            uint32_t ah[2][4], al[2][4], bh[4][2], bl[4][2];
#pragma unroll
            for (int mt = 0; mt < 2; mt++) {
                int m = wm * 32 + mt * 16 + g;
                ah[mt][0] = __float_as_uint(Ah[ks + q][m]);
                ah[mt][1] = __float_as_uint(Ah[ks + q][m + 8]);
                ah[mt][2] = __float_as_uint(Ah[ks + q + 4][m]);
                ah[mt][3] = __float_as_uint(Ah[ks + q + 4][m + 8]);
                al[mt][0] = __float_as_uint(Al[ks + q][m]);
                al[mt][1] = __float_as_uint(Al[ks + q][m + 8]);
                al[mt][2] = __float_as_uint(Al[ks + q + 4][m]);
                al[mt][3] = __float_as_uint(Al[ks + q + 4][m + 8]);
            }
#pragma unroll
            for (int nt = 0; nt < 4; nt++) {
                int n = wn * 32 + nt * 8 + g;
                bh[nt][0] = __float_as_uint(Bh[ks + q][n]);
                bh[nt][1] = __float_as_uint(Bh[ks + q + 4][n]);
                bl[nt][0] = __float_as_uint(Bl[ks + q][n]);
                bl[nt][1] = __float_as_uint(Bl[ks + q + 4][n]);
            }
#pragma unroll
            for (int mt = 0; mt < 2; mt++) {
#pragma unroll
                for (int nt = 0; nt < 4; nt++) {
                    float* c = acc[mt][nt];
#define MMA(AA, BB) \
    asm volatile("mma.sync.aligned.m16n8k8.row.col.f32.tf32.tf32.f32 " \
                 "{%0,%1,%2,%3}, {%4,%5,%6,%7}, {%8,%9}, {%0,%1,%2,%3};" \
                 : "+f"(c[0]), "+f"(c[1]), "+f"(c[2]), "+f"(c[3]) \
                 : "r"(AA[0]), "r"(AA[1]), "r"(AA[2]), "r"(AA[3]), "r"(BB[0]), "r"(BB[1]))
                    MMA(ah[mt], bh[nt]);
                    MMA(al[mt], bh[nt]);
                    MMA(ah[mt], bl[nt]);
#undef MMA
                }
            }
        }
        __syncthreads();
    }

    // ---- epilogue ----
#pragma unroll
    for (int nt = 0; nt < 4; nt++) {
        int col = colBase + wn * 32 + nt * 8 + q * 2;
        if (col >= Nc) continue;   // Nc even, col even -> col+1 also valid
        float bia0 = bias[col], bia1 = bias[col + 1];
        float sc0 = 1.f, sc1 = 1.f, sh0 = 0.f, sh1 = 0.f;
        if (MODE >= 2) {
            sc0 = bng[col] * rsqrtf(bnv[col] + BN_EPS);
            sc1 = bng[col + 1] * rsqrtf(bnv[col + 1] + BN_EPS);
            sh0 = bnb[col] - bnm[col] * sc0;
            sh1 = bnb[col + 1] - bnm[col + 1] * sc1;
        }
#pragma unroll
        for (int mt = 0; mt < 2; mt++) {
            float* c = acc[mt][nt];
#pragma unroll
            for (int half = 0; half < 2; half++) {
                int r = rowBase + wm * 32 + mt * 16 + g + half * 8;
                if (r >= M) continue;
                float v0 = c[half * 2 + 0] + bia0;
                float v1 = c[half * 2 + 1] + bia1;
                if (MODE >= 2) { v0 = v0 * sc0 + sh0; v1 = v1 * sc1 + sh1; }
                if (MODE == 1 || MODE == 3) { v0 = fmaxf(v0, 0.f); v1 = fmaxf(v1, 0.f); }
                *(float2*)(C + (size_t)r * Nc + col) = make_float2(v0, v1);
            }
        }
    }
}

// ---------------- avg pool per graph (graph_ids sorted -> contiguous ranges) ----------------
__device__ __forceinline__ int lower_bound_dev(const int* a, int n, int v) {
    int lo = 0, hi = n;
    while (lo < hi) {
        int m = (lo + hi) >> 1;
        if (a[m] < v) lo = m + 1; else hi = m;
    }
    return lo;
}

__global__ void pool_kernel(const float* __restrict__ h, const int* __restrict__ gid,
                            float* __restrict__ gavg, int N) {
    __shared__ int sh[2];
    int g = blockIdx.x;
    if (threadIdx.x == 0) sh[0] = lower_bound_dev(gid, N, g);
    if (threadIdx.x == 1) sh[1] = lower_bound_dev(gid, N, g + 1);
    __syncthreads();
    int lo = sh[0], hi = sh[1];
    int d = threadIdx.x;
    if (d >= D) return;
    float s = 0.f;
    for (int n = lo; n < hi; n++) s += h[(size_t)n * D + d];
    float cnt = (float)(hi - lo);
    gavg[(size_t)g * D + d] = s / fmaxf(cnt, 1.0f);
}

// ---------------- small fp32 GEMM for the head ----------------
__global__ __launch_bounds__(256)
void head_gemm_kernel(const float* __restrict__ A, const float* __restrict__ B,
                      const float* __restrict__ bias, float* __restrict__ C,
                      int M, int K, int Nc) {
    // one block per 16 rows x 64 cols; simple but the head is tiny
    int row = blockIdx.y * 16 + (threadIdx.x >> 4);
    int col = blockIdx.x * 64 + (threadIdx.x & 15) * 4;
    if (row >= M || col >= Nc) return;
    float s0 = 0.f, s1 = 0.f, s2 = 0.f, s3 = 0.f;
    const float* a = A + (size_t)row * K;
    for (int k = 0; k < K; k++) {
        float av = a[k];
        const float* b = B + (size_t)k * Nc + col;
        s0 += av * b[0]; s1 += av * b[1]; s2 += av * b[2]; s3 += av * b[3];
    }
    float* out = C + (size_t)row * Nc + col;
    out[0] = s0 + bias[col];
    out[1] = s1 + bias[col + 1];
    out[2] = s2 + bias[col + 2];
    out[3] = s3 + bias[col + 3];
}

// ---------------- launch ----------------
extern "C" void kernel_launch(void* const* d_in, const int* in_sizes, int n_in,
                              void* d_out, int out_size) {
    const int* an  = (const int*)d_in[0];
    const int* ct  = (const int*)d_in[1];
    const int* bt  = (const int*)d_in[2];
    const int* bdt = (const int*)d_in[3];
    const int* src = (const int*)d_in[4];
    const int* dst = (const int*)d_in[5];
    const int* gid = (const int*)d_in[6];
    const int N = in_sizes[0];
    const int E = in_sizes[2];

    int p = 7;
    if (n_in > 7 && in_sizes[7] == 1) p = 8;
    const float* node_emb0 = (const float*)d_in[p + 0];
    const float* node_emb1 = (const float*)d_in[p + 1];
    const float* edge_emb0 = (const float*)d_in[p + 2];
    const float* edge_emb1 = (const float*)d_in[p + 3];
    const float* W1  = (const float*)d_in[p + 4];
    const float* b1  = (const float*)d_in[p + 5];
    const float* W2  = (const float*)d_in[p + 6];
    const float* b2  = (const float*)d_in[p + 7];
    const float* bng = (const float*)d_in[p + 8];
    const float* bnb = (const float*)d_in[p + 9];
    const float* bnm = (const float*)d_in[p + 10];
    const float* bnv = (const float*)d_in[p + 11];
    const float* Wd  = (const float*)d_in[p + 12];
    const float* bd  = (const float*)d_in[p + 13];
    const int G = out_size / 256;

    float *h, *agg, *t, *cnt0, *cnt1, *gavg;
    cudaGetSymbolAddress((void**)&h, g_h);
    cudaGetSymbolAddress((void**)&agg, g_agg);
    cudaGetSymbolAddress((void**)&t, g_t);
    cudaGetSymbolAddress((void**)&cnt0, g_cnt0);
    cudaGetSymbolAddress((void**)&cnt1, g_cnt1);
    cudaGetSymbolAddress((void**)&gavg, g_gavg);

    const int ND = N * D;

    // once-per-call precomputation
    zero_kernel<<<(N * 9 + 255) / 256, 256>>>(cnt0, N * 6);           // cnt0
    zero_kernel<<<(N * 3 + 255) / 256, 256>>>(cnt1, N * 3);           // cnt1
    count_kernel<<<(E + 255) / 256, 256>>>(bt, bdt, dst, cnt0, cnt1, E);
    init_h_kernel<<<(ND + 255) / 256, 256>>>(an, ct, node_emb0, node_emb1, h, N);

    dim3 g1((TWO_D + BN - 1) / BN, (N + BM - 1) / BM);
    dim3 g2((D + BN - 1) / BN, (N + BM - 1) / BM);

    for (int l = 0; l < NLAYERS; l++) {
        agg_init_kernel<<<(N * 75 + 255) / 256, 256>>>(
            cnt0, cnt1, edge_emb0 + (size_t)l * 6 * D, edge_emb1 + (size_t)l * 3 * D, agg, N);
        scatter_h_kernel<<<(E * 75 + 255) / 256, 256>>>(h, src, dst, agg, E);
        // t = relu(agg @ W1[l] + b1[l])      [N, 600]
        gemm_tf32_kernel<1><<<g1, 256>>>(
            agg, W1 + (size_t)l * D * TWO_D, b1 + (size_t)l * TWO_D,
            nullptr, nullptr, nullptr, nullptr, t, N, D, TWO_D);
        // h = [relu(]bn(t @ W2[l] + b2[l])[)]   [N, 300]
        if (l < NLAYERS - 1) {
            gemm_tf32_kernel<3><<<g2, 256>>>(
                t, W2 + (size_t)l * TWO_D * D, b2 + (size_t)l * D,
                bng + (size_t)l * D, bnb + (size_t)l * D,
                bnm + (size_t)l * D, bnv + (size_t)l * D, h, N, TWO_D, D);
        } else {
            gemm_tf32_kernel<2><<<g2, 256>>>(
                t, W2 + (size_t)l * TWO_D * D, b2 + (size_t)l * D,
                bng + (size_t)l * D, bnb + (size_t)l * D,
                bnm + (size_t)l * D, bnv + (size_t)l * D, h, N, TWO_D, D);
        }
    }

    pool_kernel<<<G, 320>>>(h, gid, gavg, N);
    head_gemm_kernel<<<dim3(256 / 64, (G + 15) / 16), 256>>>(gavg, Wd, bd, (float*)d_out, G, D, 256);
}

// round 3
// speedup vs baseline: 1.1664x; 1.0933x over previous
#include <cuda_runtime.h>
#include <cstdint>

#define D 300
#define TWO_D 600
#define NLAYERS 5
#define MAXN 200000
#define MAXG 1024
#define BN_EPS 1e-5f

// ---------------- scratch (allocation-free: __device__ globals) ----------------
__device__ float g_h[(size_t)MAXN * D];
__device__ float g_agg[(size_t)MAXN * D];
__device__ float g_t[(size_t)MAXN * TWO_D];
__device__ float g_cnt[(size_t)MAXN * 9];
__device__ float g_gavg[(size_t)MAXG * D];

// ---------------- helpers ----------------
__device__ __forceinline__ float tf32_rna(float x) {
    uint32_t u;
    asm("cvt.rna.tf32.f32 %0, %1;" : "=r"(u) : "f"(x));
    return __uint_as_float(u);
}

// ---------------- zero ----------------
__global__ void zero_kernel(float* __restrict__ p, int n) {
    int i = blockIdx.x * blockDim.x + threadIdx.x;
    if (i < n) p[i] = 0.f;
}

// ---------------- h0 = node_emb0[an] + node_emb1[ct] ----------------
__global__ void init_h_kernel(const int* __restrict__ an, const int* __restrict__ ct,
                              const float* __restrict__ e0, const float* __restrict__ e1,
                              float* __restrict__ h, int N) {
    int idx = blockIdx.x * blockDim.x + threadIdx.x;
    if (idx >= N * D) return;
    int n = idx / D;
    int d = idx - n * D;
    h[idx] = e0[an[n] * D + d] + e1[ct[n] * D + d];
}

// ---------------- per-dst counts of bond-type / bond-direction ----------------
__global__ void count_kernel(const int* __restrict__ bt, const int* __restrict__ bdt,
                             const int* __restrict__ dst, float* __restrict__ cnt, int E) {
    int e = blockIdx.x * blockDim.x + threadIdx.x;
    if (e >= E) return;
    int d = dst[e];
    atomicAdd(&cnt[d * 9 + bt[e]], 1.f);
    atomicAdd(&cnt[d * 9 + 6 + bdt[e]], 1.f);
}

// ---------------- agg = cnt0 @ e0[l] + cnt1 @ e1[l] ----------------
__global__ void agg_init_kernel(const float* __restrict__ cnt,
                                const float* __restrict__ e0, const float* __restrict__ e1,
                                float* __restrict__ agg, int N) {
    int idx = blockIdx.x * blockDim.x + threadIdx.x;
    if (idx >= N * 75) return;
    int n = idx / 75;
    int c = idx - n * 75;
    float4 s = make_float4(0.f, 0.f, 0.f, 0.f);
#pragma unroll
    for (int b = 0; b < 6; b++) {
        float w = cnt[n * 9 + b];
        if (w != 0.f) {
            float4 v = *(const float4*)(e0 + (size_t)b * D + c * 4);
            s.x += w * v.x; s.y += w * v.y; s.z += w * v.z; s.w += w * v.w;
        }
    }
#pragma unroll
    for (int b = 0; b < 3; b++) {
        float w = cnt[n * 9 + 6 + b];
        if (w != 0.f) {
            float4 v = *(const float4*)(e1 + (size_t)b * D + c * 4);
            s.x += w * v.x; s.y += w * v.y; s.z += w * v.z; s.w += w * v.w;
        }
    }
    *(float4*)(agg + (size_t)n * D + c * 4) = s;
}

// ---------------- scatter: agg[dst] += h[src] via vectorized red ----------------
__global__ void scatter_h_kernel(const float* __restrict__ h,
                                 const int* __restrict__ src, const int* __restrict__ dst,
                                 float* __restrict__ agg, int E) {
    int idx = blockIdx.x * blockDim.x + threadIdx.x;
    if (idx >= E * 75) return;
    int e = idx / 75;
    int c = idx - e * 75;
    float4 hv = *(const float4*)(h + (size_t)src[e] * D + c * 4);
    float* out = agg + (size_t)dst[e] * D + c * 4;
    asm volatile("red.global.add.v4.f32 [%0], {%1,%2,%3,%4};"
                 :: "l"(out), "f"(hv.x), "f"(hv.y), "f"(hv.z), "f"(hv.w) : "memory");
}

// ---------------- TF32 tensor-core GEMM, fragment-major smem, double-buffered ----------------
// C = epilogue(A[M,K] @ B[K,Nc] + bias)
// MODE 0: bias; 1: bias+relu; 2: bias+bn; 3: bias+bn+relu
#define BM 128
#define BN 64
#define BK 16

// A smem: fragment-major. aoff(stage,kt,mt,lane,e) floats.
#define A_KT 1032          // 8 mtiles * 128 floats + 8 pad (kills STS kt-conflicts)
#define A_STAGE (2 * A_KT)
#define B_KT 520           // 8 ntiles * 64 floats + 8 pad
#define B_STAGE (2 * B_KT)

template <int MODE>
__global__ __launch_bounds__(256)
void gemm_tf32_kernel(const float* __restrict__ A, const float* __restrict__ B,
                      const float* __restrict__ bias,
                      const float* __restrict__ bng, const float* __restrict__ bnb,
                      const float* __restrict__ bnm, const float* __restrict__ bnv,
                      float* __restrict__ C, int M, int K, int Nc) {
    __shared__ float As[2 * A_STAGE];   // 2 stages
    __shared__ float Bs[2 * B_STAGE];

    const int tid = threadIdx.x;
    const int lane = tid & 31;
    const int warp = tid >> 5;
    const int wm = warp >> 1;      // 0..3
    const int wn = warp & 1;       // 0..1
    const int gg = lane >> 2;      // 0..7
    const int qq = lane & 3;       // 0..3
    const int rowBase = blockIdx.y * BM;
    const int colBase = blockIdx.x * BN;

    // ---- loader index precompute ----
    // A: 2 chunks per thread
    int a_row[2], a_kc[2], a_soff[2];
#pragma unroll
    for (int i = 0; i < 2; i++) {
        int id = tid + i * 256;
        a_row[i] = id >> 2;               // 0..127
        a_kc[i] = (id & 3) * 4;           // 0,4,8,12
        int mt = a_row[i] >> 4;
        int rr = a_row[i] & 15;
        int kt = a_kc[i] >> 3;
        int kk0 = a_kc[i] & 7;            // 0 or 4
        int e = (rr >> 3) + 2 * (kk0 >> 2);
        int lanebase = (rr & 7) * 4;
        a_soff[i] = kt * A_KT + mt * 128 + lanebase * 4 + e;   // + j*4 per element
    }
    // B: 1 chunk per thread
    int b_r = tid >> 4;                   // 0..15
    int b_c4 = (tid & 15) * 4;            // 0..60
    int b_soff;
    {
        int kt = b_r >> 3;
        int kk = b_r & 7;
        int e = kk >> 2;
        int nt = b_c4 >> 3;
        int nn0 = b_c4 & 7;               // 0 or 4
        b_soff = kt * B_KT + nt * 64 + (nn0 * 4 + (kk & 3)) * 2 + e;   // + j*8 per element
    }

    float acc[2][4][4];
#pragma unroll
    for (int mt = 0; mt < 2; mt++)
#pragma unroll
        for (int nt = 0; nt < 4; nt++)
#pragma unroll
            for (int i = 0; i < 4; i++) acc[mt][nt][i] = 0.f;

    // ---- prefetch regs ----
    float4 av[2], bv;

    auto ldg_tile = [&](int k0) {
#pragma unroll
        for (int i = 0; i < 2; i++) {
            av[i] = make_float4(0.f, 0.f, 0.f, 0.f);
            int gr = rowBase + a_row[i];
            if (gr < M && k0 + a_kc[i] < K)     // K%4==0: chunk all-in or all-out
                av[i] = *(const float4*)(A + (size_t)gr * K + k0 + a_kc[i]);
        }
        bv = make_float4(0.f, 0.f, 0.f, 0.f);
        int gk = k0 + b_r;
        int gc = colBase + b_c4;
        if (gk < K && gc < Nc)                  // Nc%4==0
            bv = *(const float4*)(B + (size_t)gk * Nc + gc);
    };

    auto sts_tile = [&](int stage) {
        float* Ab = As + stage * A_STAGE;
        float* Bb = Bs + stage * B_STAGE;
#pragma unroll
        for (int i = 0; i < 2; i++) {
            float vv[4] = {av[i].x, av[i].y, av[i].z, av[i].w};
#pragma unroll
            for (int j = 0; j < 4; j++) Ab[a_soff[i] + j * 4] = vv[j];
        }
        float bb[4] = {bv.x, bv.y, bv.z, bv.w};
#pragma unroll
        for (int j = 0; j < 4; j++) Bb[b_soff + j * 8] = bb[j];
    };

    ldg_tile(0);
    sts_tile(0);
    __syncthreads();
    int stage = 0;

    const int a_base = wm * 2 * 128 + lane * 4;   // within kt region: mtiles wm*2, wm*2+1
    const int b_base = wn * 4 * 64 + lane * 2;    // ntiles wn*4 .. wn*4+3

    for (int k0 = 0; k0 < K; k0 += BK) {
        bool has_next = (k0 + BK) < K;
        if (has_next) ldg_tile(k0 + BK);

        const float* Ab = As + stage * A_STAGE;
        const float* Bb = Bs + stage * B_STAGE;
#pragma unroll
        for (int kt = 0; kt < 2; kt++) {
            uint32_t ah[2][4], al[2][4], bh[4][2], bl[4][2];
#pragma unroll
            for (int mt = 0; mt < 2; mt++) {
                float4 v = *(const float4*)(Ab + kt * A_KT + a_base + mt * 128);
                float x[4] = {v.x, v.y, v.z, v.w};
#pragma unroll
                for (int j = 0; j < 4; j++) {
                    float hi = tf32_rna(x[j]);
                    ah[mt][j] = __float_as_uint(hi);
                    al[mt][j] = __float_as_uint(x[j] - hi);
                }
            }
#pragma unroll
            for (int nt = 0; nt < 4; nt++) {
                float2 v = *(const float2*)(Bb + kt * B_KT + b_base + nt * 64);
                float x[2] = {v.x, v.y};
#pragma unroll
                for (int j = 0; j < 2; j++) {
                    float hi = tf32_rna(x[j]);
                    bh[nt][j] = __float_as_uint(hi);
                    bl[nt][j] = __float_as_uint(x[j] - hi);
                }
            }
#define MMA(CC, AA, BB) \
    asm volatile("mma.sync.aligned.m16n8k8.row.col.f32.tf32.tf32.f32 " \
                 "{%0,%1,%2,%3}, {%4,%5,%6,%7}, {%8,%9}, {%0,%1,%2,%3};" \
                 : "+f"(CC[0]), "+f"(CC[1]), "+f"(CC[2]), "+f"(CC[3]) \
                 : "r"(AA[0]), "r"(AA[1]), "r"(AA[2]), "r"(AA[3]), "r"(BB[0]), "r"(BB[1]))
#pragma unroll
            for (int mt = 0; mt < 2; mt++)
#pragma unroll
                for (int nt = 0; nt < 4; nt++) MMA(acc[mt][nt], ah[mt], bh[nt]);
#pragma unroll
            for (int mt = 0; mt < 2; mt++)
#pragma unroll
                for (int nt = 0; nt < 4; nt++) MMA(acc[mt][nt], al[mt], bh[nt]);
#pragma unroll
            for (int mt = 0; mt < 2; mt++)
#pragma unroll
                for (int nt = 0; nt < 4; nt++) MMA(acc[mt][nt], ah[mt], bl[nt]);
#undef MMA
        }

        if (has_next) {
            sts_tile(stage ^ 1);
            __syncthreads();
            stage ^= 1;
        }
    }

    // ---- epilogue ----
#pragma unroll
    for (int nt = 0; nt < 4; nt++) {
        int col = colBase + wn * 32 + nt * 8 + qq * 2;
        if (col >= Nc) continue;
        float bia0 = bias[col], bia1 = bias[col + 1];
        float sc0 = 1.f, sc1 = 1.f, sh0 = 0.f, sh1 = 0.f;
        if (MODE >= 2) {
            sc0 = bng[col] * rsqrtf(bnv[col] + BN_EPS);
            sc1 = bng[col + 1] * rsqrtf(bnv[col + 1] + BN_EPS);
            sh0 = bnb[col] - bnm[col] * sc0;
            sh1 = bnb[col + 1] - bnm[col + 1] * sc1;
        }
#pragma unroll
        for (int mt = 0; mt < 2; mt++) {
            float* c = acc[mt][nt];
#pragma unroll
            for (int half = 0; half < 2; half++) {
                int r = rowBase + wm * 32 + mt * 16 + gg + half * 8;
                if (r >= M) continue;
                float v0 = c[half * 2 + 0] + bia0;
                float v1 = c[half * 2 + 1] + bia1;
                if (MODE >= 2) { v0 = v0 * sc0 + sh0; v1 = v1 * sc1 + sh1; }
                if (MODE == 1 || MODE == 3) { v0 = fmaxf(v0, 0.f); v1 = fmaxf(v1, 0.f); }
                *(float2*)(C + (size_t)r * Nc + col) = make_float2(v0, v1);
            }
        }
    }
}

// ---------------- avg pool per graph (graph_ids sorted -> contiguous ranges) ----------------
__device__ __forceinline__ int lower_bound_dev(const int* a, int n, int v) {
    int lo = 0, hi = n;
    while (lo < hi) {
        int m = (lo + hi) >> 1;
        if (a[m] < v) lo = m + 1; else hi = m;
    }
    return lo;
}

__global__ void pool_kernel(const float* __restrict__ h, const int* __restrict__ gid,
                            float* __restrict__ gavg, int N) {
    __shared__ int sh[2];
    int g = blockIdx.x;
    if (threadIdx.x == 0) sh[0] = lower_bound_dev(gid, N, g);
    if (threadIdx.x == 1) sh[1] = lower_bound_dev(gid, N, g + 1);
    __syncthreads();
    int lo = sh[0], hi = sh[1];
    int d = threadIdx.x;
    if (d >= D) return;
    float s = 0.f;
    for (int n = lo; n < hi; n++) s += h[(size_t)n * D + d];
    float cnt = (float)(hi - lo);
    gavg[(size_t)g * D + d] = s / fmaxf(cnt, 1.0f);
}

// ---------------- small fp32 GEMM for the head ----------------
__global__ __launch_bounds__(256)
void head_gemm_kernel(const float* __restrict__ A, const float* __restrict__ B,
                      const float* __restrict__ bias, float* __restrict__ C,
                      int M, int K, int Nc) {
    int row = blockIdx.y * 16 + (threadIdx.x >> 4);
    int col = blockIdx.x * 64 + (threadIdx.x & 15) * 4;
    if (row >= M || col >= Nc) return;
    float s0 = 0.f, s1 = 0.f, s2 = 0.f, s3 = 0.f;
    const float* a = A + (size_t)row * K;
    for (int k = 0; k < K; k++) {
        float av = a[k];
        const float* b = B + (size_t)k * Nc + col;
        s0 += av * b[0]; s1 += av * b[1]; s2 += av * b[2]; s3 += av * b[3];
    }
    float* out = C + (size_t)row * Nc + col;
    out[0] = s0 + bias[col];
    out[1] = s1 + bias[col + 1];
    out[2] = s2 + bias[col + 2];
    out[3] = s3 + bias[col + 3];
}

// ---------------- launch ----------------
extern "C" void kernel_launch(void* const* d_in, const int* in_sizes, int n_in,
                              void* d_out, int out_size) {
    const int* an  = (const int*)d_in[0];
    const int* ct  = (const int*)d_in[1];
    const int* bt  = (const int*)d_in[2];
    const int* bdt = (const int*)d_in[3];
    const int* src = (const int*)d_in[4];
    const int* dst = (const int*)d_in[5];
    const int* gid = (const int*)d_in[6];
    const int N = in_sizes[0];
    const int E = in_sizes[2];

    int p = 7;
    if (n_in > 7 && in_sizes[7] == 1) p = 8;
    const float* node_emb0 = (const float*)d_in[p + 0];
    const float* node_emb1 = (const float*)d_in[p + 1];
    const float* edge_emb0 = (const float*)d_in[p + 2];
    const float* edge_emb1 = (const float*)d_in[p + 3];
    const float* W1  = (const float*)d_in[p + 4];
    const float* b1  = (const float*)d_in[p + 5];
    const float* W2  = (const float*)d_in[p + 6];
    const float* b2  = (const float*)d_in[p + 7];
    const float* bng = (const float*)d_in[p + 8];
    const float* bnb = (const float*)d_in[p + 9];
    const float* bnm = (const float*)d_in[p + 10];
    const float* bnv = (const float*)d_in[p + 11];
    const float* Wd  = (const float*)d_in[p + 12];
    const float* bd  = (const float*)d_in[p + 13];
    const int G = out_size / 256;

    float *h, *agg, *t, *cnt, *gavg;
    cudaGetSymbolAddress((void**)&h, g_h);
    cudaGetSymbolAddress((void**)&agg, g_agg);
    cudaGetSymbolAddress((void**)&t, g_t);
    cudaGetSymbolAddress((void**)&cnt, g_cnt);
    cudaGetSymbolAddress((void**)&gavg, g_gavg);

    const int ND = N * D;

    zero_kernel<<<(N * 9 + 255) / 256, 256>>>(cnt, N * 9);
    count_kernel<<<(E + 255) / 256, 256>>>(bt, bdt, dst, cnt, E);
    init_h_kernel<<<(ND + 255) / 256, 256>>>(an, ct, node_emb0, node_emb1, h, N);

    dim3 g1((TWO_D + BN - 1) / BN, (N + BM - 1) / BM);
    dim3 g2((D + BN - 1) / BN, (N + BM - 1) / BM);

    for (int l = 0; l < NLAYERS; l++) {
        agg_init_kernel<<<(N * 75 + 255) / 256, 256>>>(
            cnt, edge_emb0 + (size_t)l * 6 * D, edge_emb1 + (size_t)l * 3 * D, agg, N);
        scatter_h_kernel<<<(E * 75 + 255) / 256, 256>>>(h, src, dst, agg, E);
        gemm_tf32_kernel<1><<<g1, 256>>>(
            agg, W1 + (size_t)l * D * TWO_D, b1 + (size_t)l * TWO_D,
            nullptr, nullptr, nullptr, nullptr, t, N, D, TWO_D);
        if (l < NLAYERS - 1) {
            gemm_tf32_kernel<3><<<g2, 256>>>(
                t, W2 + (size_t)l * TWO_D * D, b2 + (size_t)l * D,
                bng + (size_t)l * D, bnb + (size_t)l * D,
                bnm + (size_t)l * D, bnv + (size_t)l * D, h, N, TWO_D, D);
        } else {
            gemm_tf32_kernel<2><<<g2, 256>>>(
                t, W2 + (size_t)l * TWO_D * D, b2 + (size_t)l * D,
                bng + (size_t)l * D, bnb + (size_t)l * D,
                bnm + (size_t)l * D, bnv + (size_t)l * D, h, N, TWO_D, D);
        }
    }

    pool_kernel<<<G, 320>>>(h, gid, gavg, N);
    head_gemm_kernel<<<dim3(256 / 64, (G + 15) / 16), 256>>>(gavg, Wd, bd, (float*)d_out, G, D, 256);
}

// round 6
// speedup vs baseline: 1.8386x; 1.5764x over previous
#include <cuda_runtime.h>
#include <cuda_fp16.h>
#include <cstdint>

#define D 300
#define TWO_D 600
#define NLAYERS 5
#define MAXN 200000
#define MAXG 1024
#define BN_EPS 1e-5f

// GEMM geometry: CTA tile 128(M) x 64(N), BK=16, 256 threads, 8 warps (4m x 2n),
// warp tile 32x32 = 2 mtiles(16) x 4 ntiles(8). mma.m16n8k16.f16, 3-way hi/lo split.
#define NT1 10                 // GEMM1: Nc=600 -> 10 n-tiles of 64
#define NKC1 19                // GEMM1: K=300 -> 19 k-chunks of 16
#define NT2 5                  // GEMM2: Nc=300
#define NKC2 38                // GEMM2: K=600
#define BTILE_WORDS 512        // B tile: 16k x 64n f16 = 1024 halves = 512 words

// ---------------- scratch (allocation-free: __device__ globals) ----------------
__device__ float g_h[(size_t)MAXN * D];
__device__ float g_agg[(size_t)MAXN * D];
__device__ float g_t[(size_t)MAXN * TWO_D];
__device__ float g_cnt[(size_t)MAXN * 9];
__device__ float g_gavg[(size_t)MAXG * D];
// fragment-major pre-split weights
__device__ uint32_t g_w1hi[(size_t)NLAYERS * NT1 * NKC1 * BTILE_WORDS];
__device__ uint32_t g_w1lo[(size_t)NLAYERS * NT1 * NKC1 * BTILE_WORDS];
__device__ uint32_t g_w2hi[(size_t)NLAYERS * NT2 * NKC2 * BTILE_WORDS];
__device__ uint32_t g_w2lo[(size_t)NLAYERS * NT2 * NKC2 * BTILE_WORDS];

// ---------------- zero ----------------
__global__ void zero_kernel(float* __restrict__ p, int n) {
    int i = blockIdx.x * blockDim.x + threadIdx.x;
    if (i < n) p[i] = 0.f;
}

// ---------------- h0 = node_emb0[an] + node_emb1[ct] ----------------
__global__ void init_h_kernel(const int* __restrict__ an, const int* __restrict__ ct,
                              const float* __restrict__ e0, const float* __restrict__ e1,
                              float* __restrict__ h, int N) {
    int idx = blockIdx.x * blockDim.x + threadIdx.x;
    if (idx >= N * D) return;
    int n = idx / D;
    int d = idx - n * D;
    h[idx] = e0[an[n] * D + d] + e1[ct[n] * D + d];
}

// ---------------- per-dst counts of bond-type / bond-direction ----------------
__global__ void count_kernel(const int* __restrict__ bt, const int* __restrict__ bdt,
                             const int* __restrict__ dst, float* __restrict__ cnt, int E) {
    int e = blockIdx.x * blockDim.x + threadIdx.x;
    if (e >= E) return;
    int d = dst[e];
    atomicAdd(&cnt[d * 9 + bt[e]], 1.f);
    atomicAdd(&cnt[d * 9 + 6 + bdt[e]], 1.f);
}

// ---------------- agg = cnt0 @ e0[l] + cnt1 @ e1[l] ----------------
__global__ void agg_init_kernel(const float* __restrict__ cnt,
                                const float* __restrict__ e0, const float* __restrict__ e1,
                                float* __restrict__ agg, int N) {
    int idx = blockIdx.x * blockDim.x + threadIdx.x;
    if (idx >= N * 75) return;
    int n = idx / 75;
    int c = idx - n * 75;
    float4 s = make_float4(0.f, 0.f, 0.f, 0.f);
#pragma unroll
    for (int b = 0; b < 6; b++) {
        float w = cnt[n * 9 + b];
        if (w != 0.f) {
            float4 v = *(const float4*)(e0 + (size_t)b * D + c * 4);
            s.x += w * v.x; s.y += w * v.y; s.z += w * v.z; s.w += w * v.w;
        }
    }
#pragma unroll
    for (int b = 0; b < 3; b++) {
        float w = cnt[n * 9 + 6 + b];
        if (w != 0.f) {
            float4 v = *(const float4*)(e1 + (size_t)b * D + c * 4);
            s.x += w * v.x; s.y += w * v.y; s.z += w * v.z; s.w += w * v.w;
        }
    }
    *(float4*)(agg + (size_t)n * D + c * 4) = s;
}

// ---------------- scatter: agg[dst] += h[src] via vectorized red ----------------
__global__ void scatter_h_kernel(const float* __restrict__ h,
                                 const int* __restrict__ src, const int* __restrict__ dst,
                                 float* __restrict__ agg, int E) {
    int idx = blockIdx.x * blockDim.x + threadIdx.x;
    if (idx >= E * 75) return;
    int e = idx / 75;
    int c = idx - e * 75;
    float4 hv = *(const float4*)(h + (size_t)src[e] * D + c * 4);
    float* out = agg + (size_t)dst[e] * D + c * 4;
    asm volatile("red.global.add.v4.f32 [%0], {%1,%2,%3,%4};"
                 :: "l"(out), "f"(hv.x), "f"(hv.y), "f"(hv.z), "f"(hv.w) : "memory");
}

// ---------------- weight prep: fragment-major f16 hi/lo split ----------------
// W gmem: [K, Nc] row-major. Output: per (ntile, kc) tile of 512 uint32 words.
// Word (nt, lane, reg): lane = g*4 + t; elements k = kc*16 + reg*8 + t*2 + {0,1},
// n = ntile*64 + nt*8 + g. half0 (low 16 bits) = even k.
__global__ void prep_w_kernel(const float* __restrict__ W,
                              uint32_t* __restrict__ ohi, uint32_t* __restrict__ olo,
                              int K, int Nc, int NKC, int total_words) {
    int w = blockIdx.x * blockDim.x + threadIdx.x;
    if (w >= total_words) return;
    int tile = w >> 9;
    int widx = w & 511;
    int ntile = tile / NKC, kc = tile - ntile * NKC;
    int nt = widx >> 6;
    int rem = widx & 63;
    int lane = rem >> 1, reg = rem & 1;
    int g = lane >> 2, t = lane & 3;
    int n = ntile * 64 + nt * 8 + g;
    int k0 = kc * 16 + reg * 8 + t * 2;
    float v0 = (n < Nc && k0 < K)     ? W[(size_t)k0 * Nc + n]       : 0.f;
    float v1 = (n < Nc && k0 + 1 < K) ? W[(size_t)(k0 + 1) * Nc + n] : 0.f;
    __half h0 = __float2half_rn(v0), h1 = __float2half_rn(v1);
    __half l0 = __float2half_rn(v0 - __half2float(h0));
    __half l1 = __float2half_rn(v1 - __half2float(h1));
    uint32_t ph = (uint32_t)__half_as_ushort(h0) | ((uint32_t)__half_as_ushort(h1) << 16);
    uint32_t pl = (uint32_t)__half_as_ushort(l0) | ((uint32_t)__half_as_ushort(l1) << 16);
    ohi[w] = ph;
    olo[w] = pl;
}

// ---------------- f16 split tensor-core GEMM ----------------
// C = epilogue(A[M,K] @ Wpre + bias)
// MODE 0: bias; 1: bias+relu; 2: bias+bn; 3: bias+bn+relu
template <int MODE>
__global__ __launch_bounds__(256)
void gemm_f16_kernel(const float* __restrict__ A,
                     const uint32_t* __restrict__ Bhi, const uint32_t* __restrict__ Blo,
                     const float* __restrict__ bias,
                     const float* __restrict__ bng, const float* __restrict__ bnb,
                     const float* __restrict__ bnm, const float* __restrict__ bnv,
                     float* __restrict__ C, int M, int K, int Nc, int NKC) {
    __shared__ float As[2][2048];        // 128 rows x 16 k fp32, fragment-major
    __shared__ uint32_t Bh[2][512];      // 16 x 64 f16 hi, fragment-major
    __shared__ uint32_t Bl[2][512];

    const int tid = threadIdx.x;
    const int lane = tid & 31;
    const int warp = tid >> 5;
    const int wm = warp >> 1;            // 0..3
    const int wn = warp & 1;             // 0..1
    const int gg = lane >> 2;            // 0..7
    const int qq = lane & 3;             // 0..3
    const int rowBase = blockIdx.y * 128;
    const int colBase = blockIdx.x * 64;

    // A loader: 2 float4 chunks per thread
    int a_row[2], a_kc[2], a_soff[2];
#pragma unroll
    for (int i = 0; i < 2; i++) {
        int id = tid + i * 256;
        a_row[i] = id >> 2;              // 0..127
        a_kc[i] = (id & 3) * 4;          // 0,4,8,12
        int r = a_row[i] & 15;
        int mt = a_row[i] >> 4;
        int rb = (r >> 3) + 2 * (a_kc[i] >> 3);
        int t0 = (a_kc[i] & 7) >> 1;
        a_soff[i] = mt * 256 + ((r & 7) * 4 + t0) * 8 + rb * 2;
    }
    const int b_sel = tid >> 7;          // 0: hi copier, 1: lo copier
    const int b_idx = tid & 127;
    const uint32_t* bthi = Bhi + (size_t)blockIdx.x * NKC * BTILE_WORDS;
    const uint32_t* btlo = Blo + (size_t)blockIdx.x * NKC * BTILE_WORDS;

    float acc[2][4][4];
#pragma unroll
    for (int mt = 0; mt < 2; mt++)
#pragma unroll
        for (int nt = 0; nt < 4; nt++)
#pragma unroll
            for (int i = 0; i < 4; i++) acc[mt][nt][i] = 0.f;

    float4 av[2];
    uint4 bv;

    auto ldg_tile = [&](int k0) {
#pragma unroll
        for (int i = 0; i < 2; i++) {
            av[i] = make_float4(0.f, 0.f, 0.f, 0.f);
            int gr = rowBase + a_row[i];
            if (gr < M && k0 + a_kc[i] < K)      // K % 4 == 0: chunk all-in/out
                av[i] = *(const float4*)(A + (size_t)gr * K + k0 + a_kc[i]);
        }
        int kc = k0 >> 4;
        const uint4* sp = (const uint4*)((b_sel ? btlo : bthi) + (size_t)kc * BTILE_WORDS);
        bv = sp[b_idx];
    };

    auto sts_tile = [&](int s) {
#pragma unroll
        for (int i = 0; i < 2; i++) {
            float* b = &As[s][a_soff[i]];
            *(float2*)b = make_float2(av[i].x, av[i].y);
            *(float2*)(b + 8) = make_float2(av[i].z, av[i].w);
        }
        uint4* dp = (uint4*)(b_sel ? Bl[s] : Bh[s]);
        dp[b_idx] = bv;
    };

    ldg_tile(0);
    sts_tile(0);
    __syncthreads();
    int stage = 0;

    for (int k0 = 0; k0 < K; k0 += 16) {
        bool has_next = (k0 + 16) < K;
        if (has_next) ldg_tile(k0 + 16);

        // ---- A fragments: load raw fp32, split to f16 hi/lo in regs ----
        uint32_t ah[2][4], al[2][4];
#pragma unroll
        for (int mt = 0; mt < 2; mt++) {
            const float* ap = &As[stage][(wm * 2 + mt) * 256 + lane * 8];
            float4 x = *(const float4*)ap;
            float4 y = *(const float4*)(ap + 4);
            float f[8] = {x.x, x.y, x.z, x.w, y.x, y.y, y.z, y.w};
#pragma unroll
            for (int r = 0; r < 4; r++) {
                __half2 hh = __floats2half2_rn(f[2 * r], f[2 * r + 1]);
                ah[mt][r] = *reinterpret_cast<uint32_t*>(&hh);
                float2 bk = __half22float2(hh);
                __half2 ll = __floats2half2_rn(f[2 * r] - bk.x, f[2 * r + 1] - bk.y);
                al[mt][r] = *reinterpret_cast<uint32_t*>(&ll);
            }
        }
        // ---- B fragments: direct LDS.64 ----
        uint32_t bh[4][2], bl[4][2];
#pragma unroll
        for (int nt = 0; nt < 4; nt++) {
            uint2 v = *(const uint2*)(&Bh[stage][(wn * 4 + nt) * 64 + lane * 2]);
            bh[nt][0] = v.x; bh[nt][1] = v.y;
            uint2 w2 = *(const uint2*)(&Bl[stage][(wn * 4 + nt) * 64 + lane * 2]);
            bl[nt][0] = w2.x; bl[nt][1] = w2.y;
        }
#define MMA(CC, AA, BB) \
    asm volatile("mma.sync.aligned.m16n8k16.row.col.f32.f16.f16.f32 " \
                 "{%0,%1,%2,%3}, {%4,%5,%6,%7}, {%8,%9}, {%0,%1,%2,%3};" \
                 : "+f"(CC[0]), "+f"(CC[1]), "+f"(CC[2]), "+f"(CC[3]) \
                 : "r"(AA[0]), "r"(AA[1]), "r"(AA[2]), "r"(AA[3]), "r"(BB[0]), "r"(BB[1]))
#pragma unroll
        for (int mt = 0; mt < 2; mt++)
#pragma unroll
            for (int nt = 0; nt < 4; nt++) MMA(acc[mt][nt], ah[mt], bh[nt]);
#pragma unroll
        for (int mt = 0; mt < 2; mt++)
#pragma unroll
            for (int nt = 0; nt < 4; nt++) MMA(acc[mt][nt], al[mt], bh[nt]);
#pragma unroll
        for (int mt = 0; mt < 2; mt++)
#pragma unroll
            for (int nt = 0; nt < 4; nt++) MMA(acc[mt][nt], ah[mt], bl[nt]);
#undef MMA

        if (has_next) {
            sts_tile(stage ^ 1);
            __syncthreads();
            stage ^= 1;
        }
    }

    // ---- epilogue ----
#pragma unroll
    for (int nt = 0; nt < 4; nt++) {
        int col = colBase + wn * 32 + nt * 8 + qq * 2;
        if (col >= Nc) continue;
        float bia0 = bias[col], bia1 = bias[col + 1];
        float sc0 = 1.f, sc1 = 1.f, sh0 = 0.f, sh1 = 0.f;
        if (MODE >= 2) {
            sc0 = bng[col] * rsqrtf(bnv[col] + BN_EPS);
            sc1 = bng[col + 1] * rsqrtf(bnv[col + 1] + BN_EPS);
            sh0 = bnb[col] - bnm[col] * sc0;
            sh1 = bnb[col + 1] - bnm[col + 1] * sc1;
        }
#pragma unroll
        for (int mt = 0; mt < 2; mt++) {
            float* c = acc[mt][nt];
#pragma unroll
            for (int half = 0; half < 2; half++) {
                int r = rowBase + wm * 32 + mt * 16 + gg + half * 8;
                if (r >= M) continue;
                float v0 = c[half * 2 + 0] + bia0;
                float v1 = c[half * 2 + 1] + bia1;
                if (MODE >= 2) { v0 = v0 * sc0 + sh0; v1 = v1 * sc1 + sh1; }
                if (MODE == 1 || MODE == 3) { v0 = fmaxf(v0, 0.f); v1 = fmaxf(v1, 0.f); }
                *(float2*)(C + (size_t)r * Nc + col) = make_float2(v0, v1);
            }
        }
    }
}

// ---------------- avg pool per graph (graph_ids sorted -> contiguous ranges) ----------------
__device__ __forceinline__ int lower_bound_dev(const int* a, int n, int v) {
    int lo = 0, hi = n;
    while (lo < hi) {
        int m = (lo + hi) >> 1;
        if (a[m] < v) lo = m + 1; else hi = m;
    }
    return lo;
}

__global__ void pool_kernel(const float* __restrict__ h, const int* __restrict__ gid,
                            float* __restrict__ gavg, int N) {
    __shared__ int sh[2];
    int g = blockIdx.x;
    if (threadIdx.x == 0) sh[0] = lower_bound_dev(gid, N, g);
    if (threadIdx.x == 1) sh[1] = lower_bound_dev(gid, N, g + 1);
    __syncthreads();
    int lo = sh[0], hi = sh[1];
    int d = threadIdx.x;
    if (d >= D) return;
    float s = 0.f;
    for (int n = lo; n < hi; n++) s += h[(size_t)n * D + d];
    float cnt = (float)(hi - lo);
    gavg[(size_t)g * D + d] = s / fmaxf(cnt, 1.0f);
}

// ---------------- small fp32 GEMM for the head ----------------
__global__ __launch_bounds__(256)
void head_gemm_kernel(const float* __restrict__ A, const float* __restrict__ B,
                      const float* __restrict__ bias, float* __restrict__ C,
                      int M, int K, int Nc) {
    int row = blockIdx.y * 16 + (threadIdx.x >> 4);
    int col = blockIdx.x * 64 + (threadIdx.x & 15) * 4;
    if (row >= M || col >= Nc) return;
    float s0 = 0.f, s1 = 0.f, s2 = 0.f, s3 = 0.f;
    const float* a = A + (size_t)row * K;
    for (int k = 0; k < K; k++) {
        float av = a[k];
        const float* b = B + (size_t)k * Nc + col;
        s0 += av * b[0]; s1 += av * b[1]; s2 += av * b[2]; s3 += av * b[3];
    }
    float* out = C + (size_t)row * Nc + col;
    out[0] = s0 + bias[col];
    out[1] = s1 + bias[col + 1];
    out[2] = s2 + bias[col + 2];
    out[3] = s3 + bias[col + 3];
}

// ---------------- launch ----------------
extern "C" void kernel_launch(void* const* d_in, const int* in_sizes, int n_in,
                              void* d_out, int out_size) {
    const int* an  = (const int*)d_in[0];
    const int* ct  = (const int*)d_in[1];
    const int* bt  = (const int*)d_in[2];
    const int* bdt = (const int*)d_in[3];
    const int* src = (const int*)d_in[4];
    const int* dst = (const int*)d_in[5];
    const int* gid = (const int*)d_in[6];
    const int N = in_sizes[0];
    const int E = in_sizes[2];

    int p = 7;
    if (n_in > 7 && in_sizes[7] == 1) p = 8;
    const float* node_emb0 = (const float*)d_in[p + 0];
    const float* node_emb1 = (const float*)d_in[p + 1];
    const float* edge_emb0 = (const float*)d_in[p + 2];
    const float* edge_emb1 = (const float*)d_in[p + 3];
    const float* W1  = (const float*)d_in[p + 4];
    const float* b1  = (const float*)d_in[p + 5];
    const float* W2  = (const float*)d_in[p + 6];
    const float* b2  = (const float*)d_in[p + 7];
    const float* bng = (const float*)d_in[p + 8];
    const float* bnb = (const float*)d_in[p + 9];
    const float* bnm = (const float*)d_in[p + 10];
    const float* bnv = (const float*)d_in[p + 11];
    const float* Wd  = (const float*)d_in[p + 12];
    const float* bd  = (const float*)d_in[p + 13];
    const int G = out_size / 256;

    float *h, *agg, *t, *cnt, *gavg;
    uint32_t *w1hi, *w1lo, *w2hi, *w2lo;
    cudaGetSymbolAddress((void**)&h, g_h);
    cudaGetSymbolAddress((void**)&agg, g_agg);
    cudaGetSymbolAddress((void**)&t, g_t);
    cudaGetSymbolAddress((void**)&cnt, g_cnt);
    cudaGetSymbolAddress((void**)&gavg, g_gavg);
    cudaGetSymbolAddress((void**)&w1hi, g_w1hi);
    cudaGetSymbolAddress((void**)&w1lo, g_w1lo);
    cudaGetSymbolAddress((void**)&w2hi, g_w2hi);
    cudaGetSymbolAddress((void**)&w2lo, g_w2lo);

    const int ND = N * D;
    const int words1 = NT1 * NKC1 * BTILE_WORDS;
    const int words2 = NT2 * NKC2 * BTILE_WORDS;

    zero_kernel<<<(N * 9 + 255) / 256, 256>>>(cnt, N * 9);
    count_kernel<<<(E + 255) / 256, 256>>>(bt, bdt, dst, cnt, E);
    init_h_kernel<<<(ND + 255) / 256, 256>>>(an, ct, node_emb0, node_emb1, h, N);

    for (int l = 0; l < NLAYERS; l++) {
        prep_w_kernel<<<(words1 + 255) / 256, 256>>>(
            W1 + (size_t)l * D * TWO_D,
            w1hi + (size_t)l * words1, w1lo + (size_t)l * words1,
            D, TWO_D, NKC1, words1);
        prep_w_kernel<<<(words2 + 255) / 256, 256>>>(
            W2 + (size_t)l * TWO_D * D,
            w2hi + (size_t)l * words2, w2lo + (size_t)l * words2,
            TWO_D, D, NKC2, words2);
    }

    const int mtiles = (N + 127) / 128;

    for (int l = 0; l < NLAYERS; l++) {
        agg_init_kernel<<<(N * 75 + 255) / 256, 256>>>(
            cnt, edge_emb0 + (size_t)l * 6 * D, edge_emb1 + (size_t)l * 3 * D, agg, N);
        scatter_h_kernel<<<(E * 75 + 255) / 256, 256>>>(h, src, dst, agg, E);
        // t = relu(agg @ W1[l] + b1[l])      [N, 600]
        gemm_f16_kernel<1><<<dim3(NT1, mtiles), 256>>>(
            agg, w1hi + (size_t)l * words1, w1lo + (size_t)l * words1,
            b1 + (size_t)l * TWO_D, nullptr, nullptr, nullptr, nullptr,
            t, N, D, TWO_D, NKC1);
        // h = [relu(]bn(t @ W2[l] + b2[l])[)]   [N, 300]
        if (l < NLAYERS - 1) {
            gemm_f16_kernel<3><<<dim3(NT2, mtiles), 256>>>(
                t, w2hi + (size_t)l * words2, w2lo + (size_t)l * words2,
                b2 + (size_t)l * D, bng + (size_t)l * D, bnb + (size_t)l * D,
                bnm + (size_t)l * D, bnv + (size_t)l * D,
                h, N, TWO_D, D, NKC2);
        } else {
            gemm_f16_kernel<2><<<dim3(NT2, mtiles), 256>>>(
                t, w2hi + (size_t)l * words2, w2lo + (size_t)l * words2,
                b2 + (size_t)l * D, bng + (size_t)l * D, bnb + (size_t)l * D,
                bnm + (size_t)l * D, bnv + (size_t)l * D,
                h, N, TWO_D, D, NKC2);
        }
    }

    pool_kernel<<<G, 320>>>(h, gid, gavg, N);
    head_gemm_kernel<<<dim3(256 / 64, (G + 15) / 16), 256>>>(gavg, Wd, bd, (float*)d_out, G, D, 256);
}

// round 8
// speedup vs baseline: 1.9769x; 1.0752x over previous
#include <cuda_runtime.h>
#include <cuda_fp16.h>
#include <cstdint>

#define D 300
#define TWO_D 600
#define NLAYERS 5
#define MAXN 200000
#define MAXG 1024
#define BN_EPS 1e-5f

#define NT1 10
#define NKC1 19
#define NT2 5
#define NKC2 38
#define BTILE_WORDS 512

// ---------------- scratch (allocation-free: __device__ globals) ----------------
__device__ float g_h[(size_t)MAXN * D];
__device__ float g_agg[(size_t)MAXN * D];
__device__ float g_t[(size_t)MAXN * TWO_D];
__device__ float g_cnt[(size_t)MAXN * 9];
__device__ float g_gavg[(size_t)MAXG * D];
__device__ uint32_t g_w1hi[(size_t)NLAYERS * NT1 * NKC1 * BTILE_WORDS];
__device__ uint32_t g_w1lo[(size_t)NLAYERS * NT1 * NKC1 * BTILE_WORDS];
__device__ uint32_t g_w2hi[(size_t)NLAYERS * NT2 * NKC2 * BTILE_WORDS];
__device__ uint32_t g_w2lo[(size_t)NLAYERS * NT2 * NKC2 * BTILE_WORDS];

// ---------------- h0 = node_emb0[an] + node_emb1[ct]  (also zeros cnt) ----------------
__global__ void init_h_zero_kernel(const int* __restrict__ an, const int* __restrict__ ct,
                                   const float* __restrict__ e0, const float* __restrict__ e1,
                                   float* __restrict__ h, float* __restrict__ cnt, int N) {
    int idx = blockIdx.x * blockDim.x + threadIdx.x;
    if (idx < N * 9) cnt[idx] = 0.f;
    if (idx >= N * D) return;
    int n = idx / D;
    int d = idx - n * D;
    h[idx] = e0[an[n] * D + d] + e1[ct[n] * D + d];
}

// ---------------- per-dst counts of bond-type / bond-direction ----------------
__global__ void count_kernel(const int* __restrict__ bt, const int* __restrict__ bdt,
                             const int* __restrict__ dst, float* __restrict__ cnt, int E) {
    int e = blockIdx.x * blockDim.x + threadIdx.x;
    if (e >= E) return;
    int d = dst[e];
    atomicAdd(&cnt[d * 9 + bt[e]], 1.f);
    atomicAdd(&cnt[d * 9 + 6 + bdt[e]], 1.f);
}

// ---------------- agg = cnt0 @ e0[l] + cnt1 @ e1[l] ----------------
__global__ void agg_init_kernel(const float* __restrict__ cnt,
                                const float* __restrict__ e0, const float* __restrict__ e1,
                                float* __restrict__ agg, int N) {
    int idx = blockIdx.x * blockDim.x + threadIdx.x;
    if (idx >= N * 75) return;
    int n = idx / 75;
    int c = idx - n * 75;
    float4 s = make_float4(0.f, 0.f, 0.f, 0.f);
#pragma unroll
    for (int b = 0; b < 6; b++) {
        float w = cnt[n * 9 + b];
        if (w != 0.f) {
            float4 v = *(const float4*)(e0 + (size_t)b * D + c * 4);
            s.x += w * v.x; s.y += w * v.y; s.z += w * v.z; s.w += w * v.w;
        }
    }
#pragma unroll
    for (int b = 0; b < 3; b++) {
        float w = cnt[n * 9 + 6 + b];
        if (w != 0.f) {
            float4 v = *(const float4*)(e1 + (size_t)b * D + c * 4);
            s.x += w * v.x; s.y += w * v.y; s.z += w * v.z; s.w += w * v.w;
        }
    }
    *(float4*)(agg + (size_t)n * D + c * 4) = s;
}

// ---------------- scatter: agg[dst] += h[src] via vectorized red ----------------
__global__ void scatter_h_kernel(const float* __restrict__ h,
                                 const int* __restrict__ src, const int* __restrict__ dst,
                                 float* __restrict__ agg, int E) {
    int idx = blockIdx.x * blockDim.x + threadIdx.x;
    if (idx >= E * 75) return;
    int e = idx / 75;
    int c = idx - e * 75;
    float4 hv = *(const float4*)(h + (size_t)src[e] * D + c * 4);
    float* out = agg + (size_t)dst[e] * D + c * 4;
    asm volatile("red.global.add.v4.f32 [%0], {%1,%2,%3,%4};"
                 :: "l"(out), "f"(hv.x), "f"(hv.y), "f"(hv.z), "f"(hv.w) : "memory");
}

// ---------------- weight prep: fragment-major f16 hi/lo split ----------------
__global__ void prep_w_kernel(const float* __restrict__ W,
                              uint32_t* __restrict__ ohi, uint32_t* __restrict__ olo,
                              int K, int Nc, int NKC, int total_words) {
    int w = blockIdx.x * blockDim.x + threadIdx.x;
    if (w >= total_words) return;
    int tile = w >> 9;
    int widx = w & 511;
    int ntile = tile / NKC, kc = tile - ntile * NKC;
    int nt = widx >> 6;
    int rem = widx & 63;
    int lane = rem >> 1, reg = rem & 1;
    int g = lane >> 2, t = lane & 3;
    int n = ntile * 64 + nt * 8 + g;
    int k0 = kc * 16 + reg * 8 + t * 2;
    float v0 = (n < Nc && k0 < K)     ? W[(size_t)k0 * Nc + n]       : 0.f;
    float v1 = (n < Nc && k0 + 1 < K) ? W[(size_t)(k0 + 1) * Nc + n] : 0.f;
    __half h0 = __float2half_rn(v0), h1 = __float2half_rn(v1);
    __half l0 = __float2half_rn(v0 - __half2float(h0));
    __half l1 = __float2half_rn(v1 - __half2float(h1));
    uint32_t ph = (uint32_t)__half_as_ushort(h0) | ((uint32_t)__half_as_ushort(h1) << 16);
    uint32_t pl = (uint32_t)__half_as_ushort(l0) | ((uint32_t)__half_as_ushort(l1) << 16);
    ohi[w] = ph;
    olo[w] = pl;
}

// ---------------- f16 split tensor-core GEMM ----------------
// A smem layout (per stage, per m-tile of 16 rows): two 128-float regions.
// region0 float4/lane: {(g,2q),(g,2q+1),(g+8,2q),(g+8,2q+1)}; region1: k+8.
// Consumer LDS.128 at 16B/lane stride -> minimal 4-phase.
template <int MODE>
__global__ __launch_bounds__(256)
void gemm_f16_kernel(const float* __restrict__ A,
                     const uint32_t* __restrict__ Bhi, const uint32_t* __restrict__ Blo,
                     const float* __restrict__ bias,
                     const float* __restrict__ bng, const float* __restrict__ bnb,
                     const float* __restrict__ bnm, const float* __restrict__ bnv,
                     float* __restrict__ C, int M, int K, int Nc, int NKC) {
    __shared__ float As[2][2048];
    __shared__ uint32_t Bh[2][512];
    __shared__ uint32_t Bl[2][512];

    const int tid = threadIdx.x;
    const int lane = tid & 31;
    const int warp = tid >> 5;
    const int wm = warp >> 1;
    const int wn = warp & 1;
    const int gg = lane >> 2;
    const int qq = lane & 3;
    const int rowBase = blockIdx.y * 128;
    const int colBase = blockIdx.x * 64;

    // A loader: 2 float4 chunks per thread
    int a_row[2], a_kc[2], a_soff[2];
#pragma unroll
    for (int i = 0; i < 2; i++) {
        int id = tid + i * 256;
        a_row[i] = id >> 2;              // 0..127
        a_kc[i] = (id & 3) * 4;          // 0,4,8,12
        int mt = a_row[i] >> 4;
        int rr = a_row[i] & 15;
        int r7 = rr & 7, rh = rr >> 3;
        int q0 = (a_kc[i] & 7) >> 1;     // 0 or 2
        a_soff[i] = mt * 256 + ((a_kc[i] & 8) ? 128 : 0) + (r7 * 4 + q0) * 4 + 2 * rh;
    }
    const int b_sel = tid >> 7;
    const int b_idx = tid & 127;
    const uint32_t* bthi = Bhi + (size_t)blockIdx.x * NKC * BTILE_WORDS;
    const uint32_t* btlo = Blo + (size_t)blockIdx.x * NKC * BTILE_WORDS;

    float acc[2][4][4];
#pragma unroll
    for (int mt = 0; mt < 2; mt++)
#pragma unroll
        for (int nt = 0; nt < 4; nt++)
#pragma unroll
            for (int i = 0; i < 4; i++) acc[mt][nt][i] = 0.f;

    float4 av[2];
    uint4 bv;

    auto ldg_tile = [&](int k0) {
#pragma unroll
        for (int i = 0; i < 2; i++) {
            av[i] = make_float4(0.f, 0.f, 0.f, 0.f);
            int gr = rowBase + a_row[i];
            if (gr < M && k0 + a_kc[i] < K)
                av[i] = *(const float4*)(A + (size_t)gr * K + k0 + a_kc[i]);
        }
        int kc = k0 >> 4;
        const uint4* sp = (const uint4*)((b_sel ? btlo : bthi) + (size_t)kc * BTILE_WORDS);
        bv = sp[b_idx];
    };

    auto sts_tile = [&](int s) {
#pragma unroll
        for (int i = 0; i < 2; i++) {
            float* b = &As[s][a_soff[i]];
            *(float2*)b = make_float2(av[i].x, av[i].y);         // k even,odd (lane q0)
            *(float2*)(b + 4) = make_float2(av[i].z, av[i].w);   // lane q0+1
        }
        uint4* dp = (uint4*)(b_sel ? Bl[s] : Bh[s]);
        dp[b_idx] = bv;
    };

    ldg_tile(0);
    sts_tile(0);
    __syncthreads();
    int stage = 0;

    for (int k0 = 0; k0 < K; k0 += 16) {
        bool has_next = (k0 + 16) < K;
        if (has_next) ldg_tile(k0 + 16);

        uint32_t ah[2][4], al[2][4];
#pragma unroll
        for (int mt = 0; mt < 2; mt++) {
            const float* ap = &As[stage][(wm * 2 + mt) * 256 + lane * 4];
            float4 x = *(const float4*)ap;           // f0..f3
            float4 y = *(const float4*)(ap + 128);   // f4..f7 (k+8)
            float f[8] = {x.x, x.y, x.z, x.w, y.x, y.y, y.z, y.w};
#pragma unroll
            for (int r = 0; r < 4; r++) {
                __half2 hh = __floats2half2_rn(f[2 * r], f[2 * r + 1]);
                ah[mt][r] = *reinterpret_cast<uint32_t*>(&hh);
                float2 bk = __half22float2(hh);
                __half2 ll = __floats2half2_rn(f[2 * r] - bk.x, f[2 * r + 1] - bk.y);
                al[mt][r] = *reinterpret_cast<uint32_t*>(&ll);
            }
        }
        uint32_t bh[4][2], bl[4][2];
#pragma unroll
        for (int nt = 0; nt < 4; nt++) {
            uint2 v = *(const uint2*)(&Bh[stage][(wn * 4 + nt) * 64 + lane * 2]);
            bh[nt][0] = v.x; bh[nt][1] = v.y;
            uint2 w2 = *(const uint2*)(&Bl[stage][(wn * 4 + nt) * 64 + lane * 2]);
            bl[nt][0] = w2.x; bl[nt][1] = w2.y;
        }
#define MMA(CC, AA, BB) \
    asm volatile("mma.sync.aligned.m16n8k16.row.col.f32.f16.f16.f32 " \
                 "{%0,%1,%2,%3}, {%4,%5,%6,%7}, {%8,%9}, {%0,%1,%2,%3};" \
                 : "+f"(CC[0]), "+f"(CC[1]), "+f"(CC[2]), "+f"(CC[3]) \
                 : "r"(AA[0]), "r"(AA[1]), "r"(AA[2]), "r"(AA[3]), "r"(BB[0]), "r"(BB[1]))
#pragma unroll
        for (int mt = 0; mt < 2; mt++)
#pragma unroll
            for (int nt = 0; nt < 4; nt++) MMA(acc[mt][nt], ah[mt], bh[nt]);
#pragma unroll
        for (int mt = 0; mt < 2; mt++)
#pragma unroll
            for (int nt = 0; nt < 4; nt++) MMA(acc[mt][nt], al[mt], bh[nt]);
#pragma unroll
        for (int mt = 0; mt < 2; mt++)
#pragma unroll
            for (int nt = 0; nt < 4; nt++) MMA(acc[mt][nt], ah[mt], bl[nt]);
#undef MMA

        if (has_next) {
            sts_tile(stage ^ 1);
            __syncthreads();
            stage ^= 1;
        }
    }

    // ---- epilogue ----
#pragma unroll
    for (int nt = 0; nt < 4; nt++) {
        int col = colBase + wn * 32 + nt * 8 + qq * 2;
        if (col >= Nc) continue;
        float bia0 = bias[col], bia1 = bias[col + 1];
        float sc0 = 1.f, sc1 = 1.f, sh0 = 0.f, sh1 = 0.f;
        if (MODE >= 2) {
            sc0 = bng[col] * rsqrtf(bnv[col] + BN_EPS);
            sc1 = bng[col + 1] * rsqrtf(bnv[col + 1] + BN_EPS);
            sh0 = bnb[col] - bnm[col] * sc0;
            sh1 = bnb[col + 1] - bnm[col + 1] * sc1;
        }
#pragma unroll
        for (int mt = 0; mt < 2; mt++) {
            float* c = acc[mt][nt];
#pragma unroll
            for (int half = 0; half < 2; half++) {
                int r = rowBase + wm * 32 + mt * 16 + gg + half * 8;
                if (r >= M) continue;
                float v0 = c[half * 2 + 0] + bia0;
                float v1 = c[half * 2 + 1] + bia1;
                if (MODE >= 2) { v0 = v0 * sc0 + sh0; v1 = v1 * sc1 + sh1; }
                if (MODE == 1 || MODE == 3) { v0 = fmaxf(v0, 0.f); v1 = fmaxf(v1, 0.f); }
                *(float2*)(C + (size_t)r * Nc + col) = make_float2(v0, v1);
            }
        }
    }
}

// ---------------- avg pool per graph ----------------
__device__ __forceinline__ int lower_bound_dev(const int* a, int n, int v) {
    int lo = 0, hi = n;
    while (lo < hi) {
        int m = (lo + hi) >> 1;
        if (a[m] < v) lo = m + 1; else hi = m;
    }
    return lo;
}

__global__ void pool_kernel(const float* __restrict__ h, const int* __restrict__ gid,
                            float* __restrict__ gavg, int N) {
    __shared__ int sh[2];
    int g = blockIdx.x;
    if (threadIdx.x == 0) sh[0] = lower_bound_dev(gid, N, g);
    if (threadIdx.x == 1) sh[1] = lower_bound_dev(gid, N, g + 1);
    __syncthreads();
    int lo = sh[0], hi = sh[1];
    int d = threadIdx.x;
    if (d >= D) return;
    float s = 0.f;
    for (int n = lo; n < hi; n++) s += h[(size_t)n * D + d];
    float cnt = (float)(hi - lo);
    gavg[(size_t)g * D + d] = s / fmaxf(cnt, 1.0f);
}

// ---------------- small fp32 GEMM for the head ----------------
__global__ __launch_bounds__(256)
void head_gemm_kernel(const float* __restrict__ A, const float* __restrict__ B,
                      const float* __restrict__ bias, float* __restrict__ C,
                      int M, int K, int Nc) {
    int row = blockIdx.y * 16 + (threadIdx.x >> 4);
    int col = blockIdx.x * 64 + (threadIdx.x & 15) * 4;
    if (row >= M || col >= Nc) return;
    float s0 = 0.f, s1 = 0.f, s2 = 0.f, s3 = 0.f;
    const float* a = A + (size_t)row * K;
    for (int k = 0; k < K; k++) {
        float av = a[k];
        const float* b = B + (size_t)k * Nc + col;
        s0 += av * b[0]; s1 += av * b[1]; s2 += av * b[2]; s3 += av * b[3];
    }
    float* out = C + (size_t)row * Nc + col;
    out[0] = s0 + bias[col];
    out[1] = s1 + bias[col + 1];
    out[2] = s2 + bias[col + 2];
    out[3] = s3 + bias[col + 3];
}

// ---------------- launch ----------------
extern "C" void kernel_launch(void* const* d_in, const int* in_sizes, int n_in,
                              void* d_out, int out_size) {
    const int* an  = (const int*)d_in[0];
    const int* ct  = (const int*)d_in[1];
    const int* bt  = (const int*)d_in[2];
    const int* bdt = (const int*)d_in[3];
    const int* src = (const int*)d_in[4];
    const int* dst = (const int*)d_in[5];
    const int* gid = (const int*)d_in[6];
    const int N = in_sizes[0];
    const int E = in_sizes[2];

    int p = 7;
    if (n_in > 7 && in_sizes[7] == 1) p = 8;
    const float* node_emb0 = (const float*)d_in[p + 0];
    const float* node_emb1 = (const float*)d_in[p + 1];
    const float* edge_emb0 = (const float*)d_in[p + 2];
    const float* edge_emb1 = (const float*)d_in[p + 3];
    const float* W1  = (const float*)d_in[p + 4];
    const float* b1  = (const float*)d_in[p + 5];
    const float* W2  = (const float*)d_in[p + 6];
    const float* b2  = (const float*)d_in[p + 7];
    const float* bng = (const float*)d_in[p + 8];
    const float* bnb = (const float*)d_in[p + 9];
    const float* bnm = (const float*)d_in[p + 10];
    const float* bnv = (const float*)d_in[p + 11];
    const float* Wd  = (const float*)d_in[p + 12];
    const float* bd  = (const float*)d_in[p + 13];
    const int G = out_size / 256;

    float *h, *agg, *t, *cnt, *gavg;
    uint32_t *w1hi, *w1lo, *w2hi, *w2lo;
    cudaGetSymbolAddress((void**)&h, g_h);
    cudaGetSymbolAddress((void**)&agg, g_agg);
    cudaGetSymbolAddress((void**)&t, g_t);
    cudaGetSymbolAddress((void**)&cnt, g_cnt);
    cudaGetSymbolAddress((void**)&gavg, g_gavg);
    cudaGetSymbolAddress((void**)&w1hi, g_w1hi);
    cudaGetSymbolAddress((void**)&w1lo, g_w1lo);
    cudaGetSymbolAddress((void**)&w2hi, g_w2hi);
    cudaGetSymbolAddress((void**)&w2lo, g_w2lo);

    const int ND = N * D;
    const int words1 = NT1 * NKC1 * BTILE_WORDS;
    const int words2 = NT2 * NKC2 * BTILE_WORDS;
    const int mtiles = (N + 127) / 128;

    // Launch order chosen so launch #6 (ncu -s 5 -c 1) is gemm_f16<1> layer 0.
    init_h_zero_kernel<<<(ND + 255) / 256, 256>>>(an, ct, node_emb0, node_emb1, h, cnt, N);  // 1
    count_kernel<<<(E + 255) / 256, 256>>>(bt, bdt, dst, cnt, E);                            // 2

    for (int l = 0; l < NLAYERS; l++) {
        prep_w_kernel<<<(words1 + 255) / 256, 256>>>(                                        // 3
            W1 + (size_t)l * D * TWO_D,
            w1hi + (size_t)l * words1, w1lo + (size_t)l * words1,
            D, TWO_D, NKC1, words1);
        agg_init_kernel<<<(N * 75 + 255) / 256, 256>>>(                                      // 4
            cnt, edge_emb0 + (size_t)l * 6 * D, edge_emb1 + (size_t)l * 3 * D, agg, N);
        scatter_h_kernel<<<(E * 75 + 255) / 256, 256>>>(h, src, dst, agg, E);                // 5
        gemm_f16_kernel<1><<<dim3(NT1, mtiles), 256>>>(                                      // 6 <- profiled
            agg, w1hi + (size_t)l * words1, w1lo + (size_t)l * words1,
            b1 + (size_t)l * TWO_D, nullptr, nullptr, nullptr, nullptr,
            t, N, D, TWO_D, NKC1);
        prep_w_kernel<<<(words2 + 255) / 256, 256>>>(
            W2 + (size_t)l * TWO_D * D,
            w2hi + (size_t)l * words2, w2lo + (size_t)l * words2,
            TWO_D, D, NKC2, words2);
        if (l < NLAYERS - 1) {
            gemm_f16_kernel<3><<<dim3(NT2, mtiles), 256>>>(
                t, w2hi + (size_t)l * words2, w2lo + (size_t)l * words2,
                b2 + (size_t)l * D, bng + (size_t)l * D, bnb + (size_t)l * D,
                bnm + (size_t)l * D, bnv + (size_t)l * D,
                h, N, TWO_D, D, NKC2);
        } else {
            gemm_f16_kernel<2><<<dim3(NT2, mtiles), 256>>>(
                t, w2hi + (size_t)l * words2, w2lo + (size_t)l * words2,
                b2 + (size_t)l * D, bng + (size_t)l * D, bnb + (size_t)l * D,
                bnm + (size_t)l * D, bnv + (size_t)l * D,
                h, N, TWO_D, D, NKC2);
        }
    }

    pool_kernel<<<G, 320>>>(h, gid, gavg, N);
    head_gemm_kernel<<<dim3(256 / 64, (G + 15) / 16), 256>>>(gavg, Wd, bd, (float*)d_out, G, D, 256);
}